// round 17
// baseline (speedup 1.0000x reference)
#include <cuda_runtime.h>
#include <cuda_bf16.h>
#include <math.h>

#define NW 32
#define BB 64
#define TT 8192
#define KCH 8
#define CK (TT / KCH)     // 1024
#define KT 64             // fp32 per K-tile
#define NT (CK / KT)      // 16 tiles

typedef unsigned int u32;

__device__ float  g_pp[KCH * BB * NW * NW];    // per-chunk partials (2 MB)
__device__ float  g_pn[KCH * BB * NW * NW];
__device__ float  g_sum[KCH * 2 * BB * NW];
__device__ float  g_sq [KCH * 2 * BB * NW];
__device__ float  g_fpp[BB * NW * NW];         // per-b (1 - r) values
__device__ float  g_fpn[BB * NW * NW];
__device__ int    g_bctr[BB];                  // zero-init; self-cleaning
__device__ int    g_fctr;                      // zero-init; self-cleaning

__device__ __forceinline__ void ldsm4(u32& r0, u32& r1, u32& r2, u32& r3, u32 a) {
    asm volatile("ldmatrix.sync.aligned.m8n8.x4.shared.b16 {%0,%1,%2,%3}, [%4];"
                 : "=r"(r0), "=r"(r1), "=r"(r2), "=r"(r3) : "r"(a));
}
__device__ __forceinline__ void ldsm2(u32& r0, u32& r1, u32 a) {
    asm volatile("ldmatrix.sync.aligned.m8n8.x2.shared.b16 {%0,%1}, [%2];"
                 : "=r"(r0), "=r"(r1) : "r"(a));
}
__device__ __forceinline__ void mma16816(float* c, u32 a0, u32 a1, u32 a2, u32 a3,
                                         u32 b0, u32 b1) {
    asm volatile("mma.sync.aligned.m16n8k16.row.col.f32.bf16.bf16.f32 "
                 "{%0,%1,%2,%3}, {%4,%5,%6,%7}, {%8,%9}, {%0,%1,%2,%3};"
                 : "+f"(c[0]), "+f"(c[1]), "+f"(c[2]), "+f"(c[3])
                 : "r"(a0), "r"(a1), "r"(a2), "r"(a3), "r"(b0), "r"(b1));
}
__device__ __forceinline__ u32 bpack(float lo, float hi) {
    __nv_bfloat162 t = __float22bfloat162_rn(make_float2(lo, hi));
    return *(u32*)&t;
}

// ============================================================================
// Single kernel: bf16 mma.sync fused GEMM (PP + PN) + exact fp32 row stats.
//  - last CTA per b: folds 8 chunk-partials + stats, computes (1 - r).
//  - CTA completing the 64th b-fold: full final reduction (d -> expf ->
//    log10 scalar), written straight to out.  All sums fixed-order.
// ============================================================================
__global__ void __launch_bounds__(128, 4)
k_gemm(const float* __restrict__ P, const float* __restrict__ Q,
       float* __restrict__ out) {
    __shared__ __align__(1024) char sm[2][64 * 128];   // 2 x 8 KB
    __shared__ float s_sx[2][NW], s_rv[2][NW];
    __shared__ int s_last;
    __shared__ double s_p[4], s_n[4];

    const int tid = threadIdx.x, lane = tid & 31, wid = tid >> 5;
    const int chunk = blockIdx.x, b = blockIdx.y;

    const int lrow = tid >> 4;
    const int li   = tid & 15;
    u32 goff[8], sdst[8];
    const u32 sbase = (u32)__cvta_generic_to_shared(sm);
#pragma unroll
    for (int u = 0; u < 8; u++) {
        int n = 8 * (u & 3) + lrow;
        goff[u] = (u32)((n * BB + b) * TT + chunk * CK + li * 4);
        int R = 8 * u + lrow;
        sdst[u] = sbase + (u32)(R * 128 + ((li * 8) ^ (lrow << 4)));
    }

    const int qd = lane >> 3, il = lane & 7;
    const u32 xm = (u32)(il << 4);
    u32 aB[2], bB[2];
#pragma unroll
    for (int mt = 0; mt < 2; mt++)
        aB[mt] = sbase + (u32)((16 * mt + (qd & 1) * 8 + il) * 128);
    const u32 c16A = (u32)((qd >> 1) * 16);
#pragma unroll
    for (int nt = 0; nt < 2; nt++)
        bB[nt] = sbase + (u32)((wid * 16 + nt * 8 + il) * 128);
    const u32 c16B = (u32)(((lane >> 3) & 1) * 16);

    float C[2][2][4];
#pragma unroll
    for (int i = 0; i < 2; i++)
#pragma unroll
        for (int j = 0; j < 2; j++)
#pragma unroll
            for (int k = 0; k < 4; k++) C[i][j][k] = 0.f;

    float acs[8], acq[8];
#pragma unroll
    for (int u = 0; u < 8; u++) { acs[u] = 0.f; acq[u] = 0.f; }

#define LDU(u, t) __ldg((const float4*)(((u) < 4 ? P : Q) + goff[u] + (t) * KT))
#define STU(u, boff) do {                                                     \
        float4 vv = v[u];                                                     \
        u32 w0 = bpack(vv.x, vv.y), w1 = bpack(vv.z, vv.w);                   \
        asm volatile("st.shared.v2.b32 [%0], {%1,%2};"                        \
                     :: "r"(sdst[u] + (boff)), "r"(w0), "r"(w1));             \
        acs[u] += (vv.x + vv.y) + (vv.z + vv.w);                              \
        acq[u] = fmaf(vv.x, vv.x, acq[u]); acq[u] = fmaf(vv.y, vv.y, acq[u]); \
        acq[u] = fmaf(vv.z, vv.z, acq[u]); acq[u] = fmaf(vv.w, vv.w, acq[u]); \
    } while (0)

    float4 v[8];
#pragma unroll
    for (int u = 0; u < 8; u++) v[u] = LDU(u, 0);
#pragma unroll
    for (int u = 0; u < 8; u++) { STU(u, 0); v[u] = LDU(u, 1); }
    __syncthreads();

    for (int t = 0; t < NT; t++) {
        const u32 boff = (u32)((t & 1) * 8192);
        if (t + 1 < NT) {
            const u32 woff = (u32)(((t + 1) & 1) * 8192);
#pragma unroll
            for (int u = 0; u < 8; u++) {
                STU(u, woff);
                if (t + 2 < NT) v[u] = LDU(u, t + 2);
            }
        }
#pragma unroll
        for (int j = 0; j < 4; j++) {
            u32 a[2][4], bq[2][2];
#pragma unroll
            for (int mt = 0; mt < 2; mt++)
                ldsm4(a[mt][0], a[mt][1], a[mt][2], a[mt][3],
                      aB[mt] + boff + (((u32)(j * 32) + c16A) ^ xm));
#pragma unroll
            for (int nt = 0; nt < 2; nt++)
                ldsm2(bq[nt][0], bq[nt][1],
                      bB[nt] + boff + (((u32)(j * 32) + c16B) ^ xm));
#pragma unroll
            for (int mt = 0; mt < 2; mt++)
#pragma unroll
                for (int nt = 0; nt < 2; nt++)
                    mma16816(C[mt][nt], a[mt][0], a[mt][1], a[mt][2], a[mt][3],
                             bq[nt][0], bq[nt][1]);
        }
        __syncthreads();
    }

    // ---- write C partials (warps 0-1: PP, 2-3: PN) ----
    {
        float* g0 = (wid < 2 ? g_pp : g_pn) + ((size_t)(chunk * BB + b)) * (NW * NW);
        const int g = lane >> 2, tq = lane & 3;
        const int wcol = (wid & 1) * 16;
#pragma unroll
        for (int mt = 0; mt < 2; mt++)
#pragma unroll
            for (int nt = 0; nt < 2; nt++) {
                int row0 = 16 * mt + g;
                int cc = wcol + nt * 8 + 2 * tq;
                *(float2*)(g0 + row0 * NW + cc) = make_float2(C[mt][nt][0], C[mt][nt][1]);
                *(float2*)(g0 + (row0 + 8) * NW + cc) = make_float2(C[mt][nt][2], C[mt][nt][3]);
            }
    }

    // ---- stats writeout ----
#pragma unroll
    for (int u = 0; u < 8; u++) {
#pragma unroll
        for (int off = 1; off < 16; off <<= 1) {
            acs[u] += __shfl_xor_sync(0xffffffffu, acs[u], off);
            acq[u] += __shfl_xor_sync(0xffffffffu, acq[u], off);
        }
        if (li == 0) {
            int set = u >> 2, n = 8 * (u & 3) + lrow;
            int idx = (chunk * 2 + set) * (BB * NW) + b * NW + n;
            g_sum[idx] = acs[u];  g_sq[idx] = acq[u];
        }
    }

    // ---- last CTA for this b: fold partials + stats, compute (1 - r) ----
    __threadfence();
    __syncthreads();
    if (tid == 0) s_last = (atomicAdd(&g_bctr[b], 1) == KCH - 1);
    __syncthreads();
    if (!s_last) return;
    __threadfence();                        // acquire other CTAs' partials

    if (tid < 2 * NW) {                     // fold stats for this b -> shared
        int set = tid >> 5, n = tid & 31;
        float ss = 0.f, s2 = 0.f;
#pragma unroll
        for (int c = 0; c < KCH; c++) {
            int a = (c * 2 + set) * (BB * NW) + b * NW + n;
            ss += g_sum[a]; s2 += g_sq[a];
        }
        s_sx[set][n] = ss;
        s_rv[set][n] = rsqrtf((float)TT * s2 - ss * ss);
    }
    __syncthreads();

    {
        const float4* spp = (const float4*)g_pp;
        const float4* spn = (const float4*)g_pn;
        float4* dpp = (float4*)g_fpp;
        float4* dpn = (float4*)g_fpn;
#pragma unroll
        for (int u = 0; u < 2; u++) {
            const int i4l = u * 128 + tid;          // 0..255 within b
            const int i4 = b * 256 + i4l;
            float4 s0 = make_float4(0.f, 0.f, 0.f, 0.f);
            float4 s1 = make_float4(0.f, 0.f, 0.f, 0.f);
#pragma unroll
            for (int c = 0; c < KCH; c++) {
                float4 x = spp[c * (BB * 256) + i4];
                s0.x += x.x; s0.y += x.y; s0.z += x.z; s0.w += x.w;
                float4 y = spn[c * (BB * 256) + i4];
                s1.x += y.x; s1.y += y.y; s1.z += y.z; s1.w += y.w;
            }
            const int f0 = i4l * 4;                 // flat nm index of .x
            const int n = f0 >> 5, m0 = f0 & 31;
            const float sxn = s_sx[0][n], rvn = s_rv[0][n];
            float4 o0, o1;
            {
                float sxy[4] = {s0.x, s0.y, s0.z, s0.w};
                float res[4];
#pragma unroll
                for (int j = 0; j < 4; j++)
                    res[j] = 1.f - ((float)TT * sxy[j] - sxn * s_sx[0][m0 + j])
                                   * rvn * s_rv[0][m0 + j];
                o0 = make_float4(res[0], res[1], res[2], res[3]);
            }
            {
                float sxy[4] = {s1.x, s1.y, s1.z, s1.w};
                float res[4];
#pragma unroll
                for (int j = 0; j < 4; j++)
                    res[j] = 1.f - ((float)TT * sxy[j] - sxn * s_sx[1][m0 + j])
                                   * rvn * s_rv[1][m0 + j];
                o1 = make_float4(res[0], res[1], res[2], res[3]);
            }
            dpp[i4] = o0;
            dpn[i4] = o1;
        }
        if (tid == 0) g_bctr[b] = 0;                // self-clean for replay
    }

    // ---- globally-last fold CTA: final reduction, write scalar ----
    __threadfence();
    __syncthreads();
    if (tid == 0) s_last = (atomicAdd(&g_fctr, 1) == BB - 1);
    __syncthreads();
    if (!s_last) return;
    __threadfence();                        // acquire all (1-r) values

    double pos = 0.0, neg = 0.0;
#pragma unroll
    for (int set = 0; set < 2; set++) {
        const float4* src4 = (const float4*)(set ? g_fpn : g_fpp);
#pragma unroll
        for (int g = 0; g < 2; g++) {
            const int idx4 = g * 128 + tid;         // 0..255 (coalesced)
            float4 acc = make_float4(0.f, 0.f, 0.f, 0.f);
#pragma unroll 8
            for (int bb = 0; bb < BB; bb++) {
                float4 x = src4[bb * 256 + idx4];
                acc.x += x.x; acc.y += x.y; acc.z += x.z; acc.w += x.w;
            }
            const int f0 = idx4 * 4;
            const int n = f0 >> 5, m0 = f0 & 31;
            float dd[4] = {acc.x, acc.y, acc.z, acc.w};
#pragma unroll
            for (int j = 0; j < 4; j++) {
                float d = dd[j] * (1.f / (float)BB);
                if (set) neg += (double)expf(12.5f * d);           // 1/TAU
                else if (m0 + j > n) pos += (double)expf(12.5f * d);
            }
        }
    }
#pragma unroll
    for (int off = 16; off > 0; off >>= 1) {
        pos += __shfl_xor_sync(0xffffffffu, pos, off);
        neg += __shfl_xor_sync(0xffffffffu, neg, off);
    }
    if (lane == 0) { s_p[wid] = pos; s_n[wid] = neg; }
    __syncthreads();
    if (tid == 0) {
        double tp = s_p[0] + s_p[1] + s_p[2] + s_p[3];
        double tn = s_n[0] + s_n[1] + s_n[2] + s_n[3];
        out[0] = (float)log10(tp / tn + 1.0);
        g_fctr = 0;                                 // self-clean for replay
    }
}

extern "C" void kernel_launch(void* const* d_in, const int* in_sizes, int n_in,
                              void* d_out, int out_size) {
    const float* P = (const float*)d_in[0];
    const float* Q = (const float*)d_in[1];
    k_gemm<<<dim3(KCH, BB), 128>>>(P, Q, (float*)d_out);
}